// round 15
// baseline (speedup 1.0000x reference)
#include <cuda_runtime.h>
#include <stdint.h>

// Problem constants
#define NUM_COORDS   200000
#define FEAT_C       128
#define MAX_SELECTED 262144
#define N_ELEMS      (512 * NUM_COORDS)         // 102,400,000 mask elements
#define THREADS      512
#define ELEMS_PER_TH 32
#define ELEMS_PER_BLK (THREADS * ELEMS_PER_TH)  // 16384
#define NBLK         (N_ELEMS / ELEMS_PER_BLK)  // 6250 exactly
#define NWORDS       (N_ELEMS / 32)             // 3.2M uint32 bitmask words
#define NPART        (NWORDS / 32)              // 100,000 per-WARP partials

// Scratch (device globals). All words unconditionally overwritten every run
// -> no cross-replay state, no reset pass needed.
__device__ unsigned g_bm32[NWORDS];             // 12.8 MB bitmask
__device__ int g_partials[NPART];
__device__ int g_offsets[NPART];
__device__ int g_count;
__device__ int g_selidx[MAX_SELECTED];
__device__ unsigned g_nonconform = 0;  // 1 => byte-bools; 0 => 32-bit elems

__device__ __forceinline__ uint4 ldcs4(const uint4* p) {
    uint4 v;
    asm volatile("ld.global.cs.v4.u32 {%0,%1,%2,%3}, [%4];"
                 : "=r"(v.x), "=r"(v.y), "=r"(v.z), "=r"(v.w) : "l"(p));
    return v;
}

// ---------------------------------------------------------------------------
// Mode detection (64K-word scan = 256 KB). Word-mode masks contain only
// {0,1,0x3F800000}; byte-mode words violate w.p. ~0.006 each -> P(miss)~e^-390.
// Monotone + input-determined => replay-safe without reset.
// ---------------------------------------------------------------------------
__global__ void k_detect(const unsigned* __restrict__ w) {
    unsigned i = blockIdx.x * blockDim.x + threadIdx.x;
    unsigned bad = 0;
    for (unsigned j = i; j < (1u << 16); j += gridDim.x * blockDim.x) {
        unsigned v = w[j];
        if (v != 0u && v != 1u && v != 0x3F800000u) bad = 1u;
    }
    if (bad) g_nonconform = 1u;
}

// ---------------------------------------------------------------------------
// Pass 1: stream the 410 MB mask once (evict-first); each thread produces one
// uint32 bitmask word (32 elements); per-WARP totals. No smem, no syncthreads.
// ---------------------------------------------------------------------------
__global__ void __launch_bounds__(THREADS)
k_count(const void* __restrict__ mask) {
    const int blk = blockIdx.x, tid = threadIdx.x;
    const int lane = tid & 31;
    const int gwarp = blk * (THREADS / 32) + (tid >> 5);
    const int byte_mode = (g_nonconform != 0u);

    unsigned m = 0;
    if (byte_mode) {
        const uint4* p = (const uint4*)mask + (size_t)blk * (THREADS * 2)
                         + (size_t)tid * 2;
#pragma unroll
        for (int i = 0; i < 2; i++) {
            uint4 v = ldcs4(p + i);
            unsigned words[4] = { v.x, v.y, v.z, v.w };
#pragma unroll
            for (int j = 0; j < 4; j++)
#pragma unroll
                for (int b = 0; b < 4; b++)
                    if ((words[j] >> (8 * b)) & 0xFFu)
                        m |= 1u << (i * 16 + j * 4 + b);
        }
    } else {
        const uint4* p = (const uint4*)mask + (size_t)blk * (ELEMS_PER_BLK / 4)
                         + (size_t)tid * 8;
#pragma unroll
        for (int i = 0; i < 8; i++) {
            uint4 v = ldcs4(p + i);
            m |= (unsigned)(v.x != 0u) << (i * 4 + 0);
            m |= (unsigned)(v.y != 0u) << (i * 4 + 1);
            m |= (unsigned)(v.z != 0u) << (i * 4 + 2);
            m |= (unsigned)(v.w != 0u) << (i * 4 + 3);
        }
    }
    g_bm32[(size_t)blk * THREADS + tid] = m;    // coalesced 4B/thread

    // per-warp total only
    int s = __popc(m);
#pragma unroll
    for (int o = 16; o; o >>= 1) s += __shfl_down_sync(0xFFFFFFFFu, s, o);
    if (lane == 0) g_partials[gwarp] = s;
}

// ---------------------------------------------------------------------------
// Pass 2: single-block exclusive scan of 100,000 per-warp partials.
// Two-phase: chunk sums -> block scan -> chunk re-walk. ~800 KB traffic.
// ---------------------------------------------------------------------------
#define SCHUNK 98   // 98 * 1024 = 100352 >= 100000
__global__ void __launch_bounds__(1024)
k_scan() {
    const int tid = threadIdx.x;
    const int lane = tid & 31, wrp = tid >> 5;
    const int base = tid * SCHUNK;

    // phase 1: chunk sum
    int s = 0;
    for (int j = 0; j < SCHUNK; j++) {
        int i = base + j;
        s += (i < NPART) ? g_partials[i] : 0;
    }

    // block scan of per-thread sums (32 warps)
    int incl = s;
#pragma unroll
    for (int o = 1; o < 32; o <<= 1) {
        int t = __shfl_up_sync(0xFFFFFFFFu, incl, o);
        if (lane >= o) incl += t;
    }
    __shared__ int wsum[32];
    if (lane == 31) wsum[wrp] = incl;
    __syncthreads();

    int wb = 0, total = 0;
#pragma unroll
    for (int i = 0; i < 32; i++) {
        int w = wsum[i];
        wb += (i < wrp) ? w : 0;
        total += w;
    }
    int excl = wb + (incl - s);

    // phase 2: re-walk chunk, write exclusive offsets
    for (int j = 0; j < SCHUNK; j++) {
        int i = base + j;
        if (i < NPART) {
            int v = g_partials[i];
            g_offsets[i] = excl;
            excl += v;
        }
    }
    if (tid == 0) g_count = total;
}

// ---------------------------------------------------------------------------
// Pass 3: warp-autonomous emit — one uint32 word per thread, warp scan +
// per-warp offset. No smem, no syncthreads, no atomics.
// ---------------------------------------------------------------------------
__global__ void __launch_bounds__(THREADS)
k_emit(const int4* __restrict__ coords,
       float4* __restrict__ out_ext) {
    const int blk = blockIdx.x, tid = threadIdx.x;
    const int lane = tid & 31;
    const int gwarp = blk * (THREADS / 32) + (tid >> 5);

    const int widx = blk * THREADS + tid;
    unsigned m = g_bm32[widx];
    int cnt = __popc(m);

    int incl = cnt;
#pragma unroll
    for (int o = 1; o < 32; o <<= 1) {
        int t = __shfl_up_sync(0xFFFFFFFFu, incl, o);
        if (lane >= o) incl += t;
    }

    int pout = g_offsets[gwarp] + (incl - cnt);
    const int ebase = widx * 32;

    while (m) {
        int b = __ffs(m) - 1;
        m &= m - 1;
        if (pout < MAX_SELECTED) {
            int elem  = ebase + b;
            int coord = elem % NUM_COORDS;
            int box   = elem / NUM_COORDS;
            g_selidx[pout] = coord;
            int4 c = coords[coord];
            out_ext[pout] = make_float4((float)c.x, (float)c.y,
                                        (float)c.z, (float)box);
        }
        pout++;
    }
}

// ---------------------------------------------------------------------------
// Pass 4: feature gather — 8 rows per warp, batched loads + zero tail.
// (Traffic-bound at ~40 us; unchanged.)
// ---------------------------------------------------------------------------
#define GROWS 8
__global__ void __launch_bounds__(256)
k_gather(const float4* __restrict__ feat,
         float4* __restrict__ out_ext,
         float4* __restrict__ out_feat) {
    const int wrp  = (int)threadIdx.x >> 5;
    const int lane = (int)threadIdx.x & 31;
    const int rbase = (blockIdx.x * 8 + wrp) * GROWS;
    const int count = g_count;

    int cs[GROWS];
#pragma unroll
    for (int j = 0; j < GROWS; j++) {
        int row = rbase + j;
        cs[j] = (row < count) ? g_selidx[row] : -1;
    }

    float4 r[GROWS];
#pragma unroll
    for (int j = 0; j < GROWS; j++) {
        r[j] = (cs[j] >= 0) ? feat[(size_t)cs[j] * 32 + lane]
                            : make_float4(0.f, 0.f, 0.f, 0.f);
    }
#pragma unroll
    for (int j = 0; j < GROWS; j++) {
        int row = rbase + j;
        out_feat[(size_t)row * 32 + lane] = r[j];
        if (cs[j] < 0 && lane == 0)
            out_ext[row] = make_float4(0.f, 0.f, 0.f, 0.f);
    }
}

// ---------------------------------------------------------------------------
extern "C" void kernel_launch(void* const* d_in, const int* in_sizes, int n_in,
                              void* d_out, int out_size) {
    const int4*   coords = nullptr;
    const float4* feat   = nullptr;
    const void*   mask   = nullptr;
    for (int i = 0; i < n_in; i++) {
        if (in_sizes[i] == NUM_COORDS * 4)           coords = (const int4*)d_in[i];
        else if (in_sizes[i] == NUM_COORDS * FEAT_C) feat   = (const float4*)d_in[i];
        else if (in_sizes[i] == N_ELEMS)             mask   = d_in[i];
    }
    (void)out_size;

    float* out = (float*)d_out;
    float4* out_ext  = (float4*)out;                              // [262144,4] as floats
    float4* out_feat = (float4*)(out + 4 * (size_t)MAX_SELECTED); // [262144,128]

    k_detect<<<64, 256>>>((const unsigned*)mask);
    k_count<<<NBLK, THREADS>>>(mask);
    k_scan<<<1, 1024>>>();
    k_emit<<<NBLK, THREADS>>>(coords, out_ext);
    k_gather<<<MAX_SELECTED / (8 * GROWS), 256>>>(feat, out_ext, out_feat);
}

// round 16
// speedup vs baseline: 1.5887x; 1.5887x over previous
#include <cuda_runtime.h>
#include <stdint.h>

// Problem constants
#define NUM_COORDS   200000
#define FEAT_C       128
#define MAX_SELECTED 262144
#define N_ELEMS      (512 * NUM_COORDS)         // 102,400,000 mask elements
#define THREADS      512
#define ELEMS_PER_TH 32
#define ELEMS_PER_BLK (THREADS * ELEMS_PER_TH)  // 16384
#define NBLK         (N_ELEMS / ELEMS_PER_BLK)  // 6250 exactly
#define NWARP        (THREADS / 32)             // 16
#define NWORDS       (N_ELEMS / 32)             // 3.2M uint32 bitmask words

// Scratch (device globals). All words unconditionally overwritten every run
// -> no cross-replay state, no reset pass needed.
__device__ unsigned g_bm32[NWORDS];             // 12.8 MB bitmask
__device__ int g_wpart[NBLK * NWARP];           // per-warp counts (100,000)
__device__ int g_partials[NBLK];                // per-block counts (6,250)
__device__ int g_offsets[NBLK];                 // per-block exclusive offsets
__device__ int g_count;
__device__ int g_selidx[MAX_SELECTED];
__device__ unsigned g_nonconform = 0;  // 1 => byte-bools; 0 => 32-bit elems

// ---------------------------------------------------------------------------
// Mode detection (64K-word scan = 256 KB). Word-mode masks contain only
// {0,1,0x3F800000}; byte-mode words violate w.p. ~0.006 each.
// Monotone + input-determined => replay-safe without reset.
// ---------------------------------------------------------------------------
__global__ void k_detect(const unsigned* __restrict__ w) {
    unsigned i = blockIdx.x * blockDim.x + threadIdx.x;
    unsigned bad = 0;
    for (unsigned j = i; j < (1u << 16); j += gridDim.x * blockDim.x) {
        unsigned v = w[j];
        if (v != 0u && v != 1u && v != 0x3F800000u) bad = 1u;
    }
    if (bad) g_nonconform = 1u;
}

// ---------------------------------------------------------------------------
// Pass 1: stream the 410 MB mask once; each thread produces one uint32
// bitmask word (32 elements). Writes per-warp AND per-block totals.
// ---------------------------------------------------------------------------
__global__ void __launch_bounds__(THREADS)
k_count(const void* __restrict__ mask) {
    const int blk = blockIdx.x, tid = threadIdx.x;
    const int lane = tid & 31, wrp = tid >> 5;
    const int byte_mode = (g_nonconform != 0u);

    unsigned m = 0;
    if (byte_mode) {
        const uint4* p = (const uint4*)mask + (size_t)blk * (THREADS * 2)
                         + (size_t)tid * 2;
#pragma unroll
        for (int i = 0; i < 2; i++) {
            uint4 v = p[i];
            unsigned words[4] = { v.x, v.y, v.z, v.w };
#pragma unroll
            for (int j = 0; j < 4; j++)
#pragma unroll
                for (int b = 0; b < 4; b++)
                    if ((words[j] >> (8 * b)) & 0xFFu)
                        m |= 1u << (i * 16 + j * 4 + b);
        }
    } else {
        const uint4* p = (const uint4*)mask + (size_t)blk * (ELEMS_PER_BLK / 4)
                         + (size_t)tid * 8;
#pragma unroll
        for (int i = 0; i < 8; i++) {
            uint4 v = p[i];
            m |= (unsigned)(v.x != 0u) << (i * 4 + 0);
            m |= (unsigned)(v.y != 0u) << (i * 4 + 1);
            m |= (unsigned)(v.z != 0u) << (i * 4 + 2);
            m |= (unsigned)(v.w != 0u) << (i * 4 + 3);
        }
    }
    g_bm32[(size_t)blk * THREADS + tid] = m;    // coalesced 4B/thread

    // per-warp total
    int s = __popc(m);
#pragma unroll
    for (int o = 16; o; o >>= 1) s += __shfl_down_sync(0xFFFFFFFFu, s, o);
    __shared__ int ws[NWARP];
    if (lane == 0) {
        g_wpart[blk * NWARP + wrp] = s;
        ws[wrp] = s;
    }
    __syncthreads();
    // per-block total (one warp reduces the 16 warp sums)
    if (tid < NWARP) {
        int t = ws[tid];
#pragma unroll
        for (int o = NWARP / 2; o; o >>= 1) t += __shfl_down_sync(0xFFFFu, t, o);
        if (tid == 0) g_partials[blk] = t;
    }
}

// ---------------------------------------------------------------------------
// Pass 2: single-block exclusive scan of 6250 per-block partials
// (serial chunks of 7 + one block scan). ~3 us. (R14-proven.)
// ---------------------------------------------------------------------------
#define SCHUNK 7   // 7 * 1024 = 7168 >= 6250
__global__ void __launch_bounds__(1024)
k_scan() {
    const int tid = threadIdx.x;
    const int lane = tid & 31, wrp = tid >> 5;
    const int base = tid * SCHUNK;

    int loc[SCHUNK];
    int s = 0;
#pragma unroll
    for (int j = 0; j < SCHUNK; j++) {
        int i = base + j;
        int v = (i < NBLK) ? g_partials[i] : 0;
        loc[j] = s;
        s += v;
    }

    int incl = s;
#pragma unroll
    for (int o = 1; o < 32; o <<= 1) {
        int t = __shfl_up_sync(0xFFFFFFFFu, incl, o);
        if (lane >= o) incl += t;
    }
    __shared__ int wsum[32];
    if (lane == 31) wsum[wrp] = incl;
    __syncthreads();

    int wb = 0, total = 0;
#pragma unroll
    for (int i = 0; i < 32; i++) {
        int w = wsum[i];
        wb += (i < wrp) ? w : 0;
        total += w;
    }
    int excl = wb + (incl - s);

#pragma unroll
    for (int j = 0; j < SCHUNK; j++) {
        int i = base + j;
        if (i < NBLK) g_offsets[i] = excl + loc[j];
    }
    if (tid == 0) g_count = total;
}

// ---------------------------------------------------------------------------
// Pass 3: warp-autonomous emit. Warp base = block offset + in-warp prefix of
// the block's 16 per-warp partials (lanes 0-15 load one coalesced sector).
// No smem, no syncthreads, no atomics.
// ---------------------------------------------------------------------------
__global__ void __launch_bounds__(THREADS)
k_emit(const int4* __restrict__ coords,
       float4* __restrict__ out_ext) {
    const int blk = blockIdx.x, tid = threadIdx.x;
    const int lane = tid & 31, wrp = tid >> 5;

    const int widx = blk * THREADS + tid;
    unsigned m = g_bm32[widx];
    int cnt = __popc(m);

    // in-warp prefix of per-thread counts
    int incl = cnt;
#pragma unroll
    for (int o = 1; o < 32; o <<= 1) {
        int t = __shfl_up_sync(0xFFFFFFFFu, incl, o);
        if (lane >= o) incl += t;
    }

    // warp base within block: sum of this block's warp partials below wrp
    int wv = (lane < NWARP && lane < wrp) ? g_wpart[blk * NWARP + lane] : 0;
#pragma unroll
    for (int o = 16; o; o >>= 1) wv += __shfl_xor_sync(0xFFFFFFFFu, wv, o);

    int pout = g_offsets[blk] + wv + (incl - cnt);
    const int ebase = widx * 32;

    while (m) {
        int b = __ffs(m) - 1;
        m &= m - 1;
        if (pout < MAX_SELECTED) {
            int elem  = ebase + b;
            int coord = elem % NUM_COORDS;
            int box   = elem / NUM_COORDS;
            g_selidx[pout] = coord;
            int4 c = coords[coord];
            out_ext[pout] = make_float4((float)c.x, (float)c.y,
                                        (float)c.z, (float)box);
        }
        pout++;
    }
}

// ---------------------------------------------------------------------------
// Pass 4: feature gather — 8 rows per warp, batched loads + zero tail.
// (Traffic-bound at ~40 us; unchanged.)
// ---------------------------------------------------------------------------
#define GROWS 8
__global__ void __launch_bounds__(256)
k_gather(const float4* __restrict__ feat,
         float4* __restrict__ out_ext,
         float4* __restrict__ out_feat) {
    const int wrp  = (int)threadIdx.x >> 5;
    const int lane = (int)threadIdx.x & 31;
    const int rbase = (blockIdx.x * 8 + wrp) * GROWS;
    const int count = g_count;

    int cs[GROWS];
#pragma unroll
    for (int j = 0; j < GROWS; j++) {
        int row = rbase + j;
        cs[j] = (row < count) ? g_selidx[row] : -1;
    }

    float4 r[GROWS];
#pragma unroll
    for (int j = 0; j < GROWS; j++) {
        r[j] = (cs[j] >= 0) ? feat[(size_t)cs[j] * 32 + lane]
                            : make_float4(0.f, 0.f, 0.f, 0.f);
    }
#pragma unroll
    for (int j = 0; j < GROWS; j++) {
        int row = rbase + j;
        out_feat[(size_t)row * 32 + lane] = r[j];
        if (cs[j] < 0 && lane == 0)
            out_ext[row] = make_float4(0.f, 0.f, 0.f, 0.f);
    }
}

// ---------------------------------------------------------------------------
extern "C" void kernel_launch(void* const* d_in, const int* in_sizes, int n_in,
                              void* d_out, int out_size) {
    const int4*   coords = nullptr;
    const float4* feat   = nullptr;
    const void*   mask   = nullptr;
    for (int i = 0; i < n_in; i++) {
        if (in_sizes[i] == NUM_COORDS * 4)           coords = (const int4*)d_in[i];
        else if (in_sizes[i] == NUM_COORDS * FEAT_C) feat   = (const float4*)d_in[i];
        else if (in_sizes[i] == N_ELEMS)             mask   = d_in[i];
    }
    (void)out_size;

    float* out = (float*)d_out;
    float4* out_ext  = (float4*)out;                              // [262144,4] as floats
    float4* out_feat = (float4*)(out + 4 * (size_t)MAX_SELECTED); // [262144,128]

    k_detect<<<64, 256>>>((const unsigned*)mask);
    k_count<<<NBLK, THREADS>>>(mask);
    k_scan<<<1, 1024>>>();
    k_emit<<<NBLK, THREADS>>>(coords, out_ext);
    k_gather<<<MAX_SELECTED / (8 * GROWS), 256>>>(feat, out_ext, out_feat);
}

// round 17
// speedup vs baseline: 1.6256x; 1.0232x over previous
#include <cuda_runtime.h>
#include <stdint.h>

// Problem constants
#define NUM_COORDS   200000
#define FEAT_C       128
#define MAX_SELECTED 262144
#define N_ELEMS      (512 * NUM_COORDS)         // 102,400,000 mask elements
#define THREADS      512
#define ELEMS_PER_TH 64
#define ELEMS_PER_BLK (THREADS * ELEMS_PER_TH)  // 32768
#define NBLK         (N_ELEMS / ELEMS_PER_BLK)  // 3125 exactly
#define NWARP        (THREADS / 32)             // 16

// Scratch (device globals). All words unconditionally overwritten every run
// -> no cross-replay state, no reset pass needed.
__device__ uint2 g_bm64[N_ELEMS / 64];          // 12.8 MB bitmask (word pairs)
__device__ int g_wpart[NBLK * NWARP];           // per-warp counts (50,000)
__device__ int g_partials[NBLK];                // per-block counts (3,125)
__device__ int g_offsets[NBLK];                 // per-block exclusive offsets
__device__ int g_count;
__device__ int g_selidx[MAX_SELECTED];
__device__ unsigned g_nonconform = 0;  // 1 => byte-bools; 0 => 32-bit elems

// ---------------------------------------------------------------------------
// Mode detection (64K-word scan = 256 KB). Word-mode masks contain only
// {0,1,0x3F800000}; byte-mode words violate w.p. ~0.006 each.
// Monotone + input-determined => replay-safe without reset.
// ---------------------------------------------------------------------------
__global__ void k_detect(const unsigned* __restrict__ w) {
    unsigned i = blockIdx.x * blockDim.x + threadIdx.x;
    unsigned bad = 0;
    for (unsigned j = i; j < (1u << 16); j += gridDim.x * blockDim.x) {
        unsigned v = w[j];
        if (v != 0u && v != 1u && v != 0x3F800000u) bad = 1u;
    }
    if (bad) g_nonconform = 1u;
}

// ---------------------------------------------------------------------------
// Pass 1: stream the 410 MB mask once; each thread produces one uint2
// bitmask pair (64 elements). Writes per-warp AND per-block totals.
// ---------------------------------------------------------------------------
__global__ void __launch_bounds__(THREADS)
k_count(const void* __restrict__ mask) {
    const int blk = blockIdx.x, tid = threadIdx.x;
    const int lane = tid & 31, wrp = tid >> 5;
    const int byte_mode = (g_nonconform != 0u);

    unsigned m0 = 0, m1 = 0;
    if (byte_mode) {
        // 64 bytes = 4 x uint4
        const uint4* p = (const uint4*)mask + (size_t)blk * (THREADS * 4)
                         + (size_t)tid * 4;
#pragma unroll
        for (int i = 0; i < 4; i++) {
            uint4 v = p[i];
            unsigned words[4] = { v.x, v.y, v.z, v.w };
            unsigned part = 0;
#pragma unroll
            for (int j = 0; j < 4; j++)
#pragma unroll
                for (int b = 0; b < 4; b++)
                    if ((words[j] >> (8 * b)) & 0xFFu)
                        part |= 1u << (j * 4 + b);
            if (i < 2) m0 |= part << (i * 16);
            else       m1 |= part << ((i - 2) * 16);
        }
    } else {
        // 64 words = 16 x uint4 (MLP 16 streaming)
        const uint4* p = (const uint4*)mask + (size_t)blk * (ELEMS_PER_BLK / 4)
                         + (size_t)tid * 16;
#pragma unroll
        for (int i = 0; i < 8; i++) {
            uint4 v = p[i];
            m0 |= (unsigned)(v.x != 0u) << (i * 4 + 0);
            m0 |= (unsigned)(v.y != 0u) << (i * 4 + 1);
            m0 |= (unsigned)(v.z != 0u) << (i * 4 + 2);
            m0 |= (unsigned)(v.w != 0u) << (i * 4 + 3);
        }
#pragma unroll
        for (int i = 0; i < 8; i++) {
            uint4 v = p[8 + i];
            m1 |= (unsigned)(v.x != 0u) << (i * 4 + 0);
            m1 |= (unsigned)(v.y != 0u) << (i * 4 + 1);
            m1 |= (unsigned)(v.z != 0u) << (i * 4 + 2);
            m1 |= (unsigned)(v.w != 0u) << (i * 4 + 3);
        }
    }
    g_bm64[(size_t)blk * THREADS + tid] = make_uint2(m0, m1);  // 8B/thread

    // per-warp total
    int s = __popc(m0) + __popc(m1);
#pragma unroll
    for (int o = 16; o; o >>= 1) s += __shfl_down_sync(0xFFFFFFFFu, s, o);
    __shared__ int ws[NWARP];
    if (lane == 0) {
        g_wpart[blk * NWARP + wrp] = s;
        ws[wrp] = s;
    }
    __syncthreads();
    if (tid < NWARP) {
        int t = ws[tid];
#pragma unroll
        for (int o = NWARP / 2; o; o >>= 1) t += __shfl_down_sync(0xFFFFu, t, o);
        if (tid == 0) g_partials[blk] = t;
    }
}

// ---------------------------------------------------------------------------
// Pass 2: single-block exclusive scan of 3125 per-block partials
// (serial chunks of 4 + one block scan). ~2 us.
// ---------------------------------------------------------------------------
#define SCHUNK 4   // 4 * 1024 = 4096 >= 3125
__global__ void __launch_bounds__(1024)
k_scan() {
    const int tid = threadIdx.x;
    const int lane = tid & 31, wrp = tid >> 5;
    const int base = tid * SCHUNK;

    int loc[SCHUNK];
    int s = 0;
#pragma unroll
    for (int j = 0; j < SCHUNK; j++) {
        int i = base + j;
        int v = (i < NBLK) ? g_partials[i] : 0;
        loc[j] = s;
        s += v;
    }

    int incl = s;
#pragma unroll
    for (int o = 1; o < 32; o <<= 1) {
        int t = __shfl_up_sync(0xFFFFFFFFu, incl, o);
        if (lane >= o) incl += t;
    }
    __shared__ int wsum[32];
    if (lane == 31) wsum[wrp] = incl;
    __syncthreads();

    int wb = 0, total = 0;
#pragma unroll
    for (int i = 0; i < 32; i++) {
        int w = wsum[i];
        wb += (i < wrp) ? w : 0;
        total += w;
    }
    int excl = wb + (incl - s);

#pragma unroll
    for (int j = 0; j < SCHUNK; j++) {
        int i = base + j;
        if (i < NBLK) g_offsets[i] = excl + loc[j];
    }
    if (tid == 0) g_count = total;
}

// ---------------------------------------------------------------------------
// Pass 3: warp-autonomous emit — one uint2 (64 elements) per thread; ONE
// warp scan per 2048 elements. No smem, no syncthreads, no atomics.
// ---------------------------------------------------------------------------
__global__ void __launch_bounds__(THREADS)
k_emit(const int4* __restrict__ coords,
       float4* __restrict__ out_ext) {
    const int blk = blockIdx.x, tid = threadIdx.x;
    const int lane = tid & 31, wrp = tid >> 5;

    const int widx = blk * THREADS + tid;
    uint2 mm = g_bm64[widx];
    int cnt = __popc(mm.x) + __popc(mm.y);

    // in-warp prefix of per-thread counts
    int incl = cnt;
#pragma unroll
    for (int o = 1; o < 32; o <<= 1) {
        int t = __shfl_up_sync(0xFFFFFFFFu, incl, o);
        if (lane >= o) incl += t;
    }

    // warp base within block
    int wv = (lane < NWARP && lane < wrp) ? g_wpart[blk * NWARP + lane] : 0;
#pragma unroll
    for (int o = 16; o; o >>= 1) wv += __shfl_xor_sync(0xFFFFFFFFu, wv, o);

    int pout = g_offsets[blk] + wv + (incl - cnt);
    const int ebase = widx * 64;

#pragma unroll
    for (int h = 0; h < 2; h++) {
        unsigned m = (h == 0) ? mm.x : mm.y;
        const int hbase = ebase + h * 32;
        while (m) {
            int b = __ffs(m) - 1;
            m &= m - 1;
            if (pout < MAX_SELECTED) {
                int elem  = hbase + b;
                int coord = elem % NUM_COORDS;
                int box   = elem / NUM_COORDS;
                g_selidx[pout] = coord;
                int4 c = coords[coord];
                out_ext[pout] = make_float4((float)c.x, (float)c.y,
                                            (float)c.z, (float)box);
            }
            pout++;
        }
    }
}

// ---------------------------------------------------------------------------
// Pass 4: feature gather — 8 rows per warp, batched loads + zero tail.
// (Traffic-bound at ~40 us; unchanged.)
// ---------------------------------------------------------------------------
#define GROWS 8
__global__ void __launch_bounds__(256)
k_gather(const float4* __restrict__ feat,
         float4* __restrict__ out_ext,
         float4* __restrict__ out_feat) {
    const int wrp  = (int)threadIdx.x >> 5;
    const int lane = (int)threadIdx.x & 31;
    const int rbase = (blockIdx.x * 8 + wrp) * GROWS;
    const int count = g_count;

    int cs[GROWS];
#pragma unroll
    for (int j = 0; j < GROWS; j++) {
        int row = rbase + j;
        cs[j] = (row < count) ? g_selidx[row] : -1;
    }

    float4 r[GROWS];
#pragma unroll
    for (int j = 0; j < GROWS; j++) {
        r[j] = (cs[j] >= 0) ? feat[(size_t)cs[j] * 32 + lane]
                            : make_float4(0.f, 0.f, 0.f, 0.f);
    }
#pragma unroll
    for (int j = 0; j < GROWS; j++) {
        int row = rbase + j;
        out_feat[(size_t)row * 32 + lane] = r[j];
        if (cs[j] < 0 && lane == 0)
            out_ext[row] = make_float4(0.f, 0.f, 0.f, 0.f);
    }
}

// ---------------------------------------------------------------------------
extern "C" void kernel_launch(void* const* d_in, const int* in_sizes, int n_in,
                              void* d_out, int out_size) {
    const int4*   coords = nullptr;
    const float4* feat   = nullptr;
    const void*   mask   = nullptr;
    for (int i = 0; i < n_in; i++) {
        if (in_sizes[i] == NUM_COORDS * 4)           coords = (const int4*)d_in[i];
        else if (in_sizes[i] == NUM_COORDS * FEAT_C) feat   = (const float4*)d_in[i];
        else if (in_sizes[i] == N_ELEMS)             mask   = d_in[i];
    }
    (void)out_size;

    float* out = (float*)d_out;
    float4* out_ext  = (float4*)out;                              // [262144,4] as floats
    float4* out_feat = (float4*)(out + 4 * (size_t)MAX_SELECTED); // [262144,128]

    k_detect<<<64, 256>>>((const unsigned*)mask);
    k_count<<<NBLK, THREADS>>>(mask);
    k_scan<<<1, 1024>>>();
    k_emit<<<NBLK, THREADS>>>(coords, out_ext);
    k_gather<<<MAX_SELECTED / (8 * GROWS), 256>>>(feat, out_ext, out_feat);
}